// round 2
// baseline (speedup 1.0000x reference)
#include <cuda_runtime.h>
#include <cuda_bf16.h>
#include <cstdint>

#define SEQ    256
#define BATCH  64
#define VOCAB  128
#define EMBED  256
#define HIDDEN 1024

typedef unsigned long long u64;

// ---------------- device scratch (allocations forbidden) ----------------
__device__ float g_tab[3 * VOCAB * HIDDEN];          // input-side projections per vocab id (incl. x-bias)
__device__ float g_h0 [HIDDEN * BATCH];              // hprev transposed to [k][b]
__device__ float g_hs [(size_t)SEQ * HIDDEN * BATCH];// hidden states, [t][k][b]

// ---------------- helpers ----------------
__device__ __forceinline__ u64 pack2(float x) {
    u64 r; asm("mov.b64 %0, {%1, %1};" : "=l"(r) : "f"(x)); return r;
}
__device__ __forceinline__ void ffma2(u64& d, u64 a, u64 b) {
    asm volatile("fma.rn.f32x2 %0, %1, %2, %0;" : "+l"(d) : "l"(a), "l"(b));
}
__device__ __forceinline__ void unpack2(u64 v, float& lo, float& hi) {
    asm("mov.b64 {%0, %1}, %2;" : "=f"(lo), "=f"(hi) : "l"(v));
}
__device__ __forceinline__ void cpasync16(unsigned saddr, const void* gaddr) {
    asm volatile("cp.async.cg.shared.global [%0], [%1], 16;" :: "r"(saddr), "l"(gaddr));
}
__device__ __forceinline__ void cpcommit() { asm volatile("cp.async.commit_group;"); }

__device__ __forceinline__ float fsigmoid(float a) {
    return __fdividef(1.f, 1.f + __expf(-a));
}

// ---------------- kernel 1: vocab tables  tab[m][v][j] = emb[v].W_mx[j] + b_mx[j] ----------------
// grid (32, 3) x 256 threads. block handles 32 j rows of gate m, all 128 v.
__global__ void k_tables(const float* __restrict__ emb,
                         const float* __restrict__ rxw, const float* __restrict__ zxw,
                         const float* __restrict__ nxw,
                         const float* __restrict__ rxb, const float* __restrict__ zxb,
                         const float* __restrict__ nxb)
{
    __shared__ float sEmb[32 * 256];   // 32 KB
    const int tid  = threadIdx.x;
    const int m    = blockIdx.y;
    const int j    = blockIdx.x * 32 + (tid >> 3);
    const int lane = tid & 7;

    const float* W = (m == 0) ? rxw : (m == 1) ? zxw : nxw;
    const float* B = (m == 0) ? rxb : (m == 1) ? zxb : nxb;

    // this thread's 32-element k-slice of W[j]: k = lane + 8*i
    float wreg[32];
#pragma unroll
    for (int i = 0; i < 32; i++) wreg[i] = W[j * EMBED + lane + 8 * i];
    const float bias = B[j];

    for (int p = 0; p < 4; p++) {                // vocab phases of 32
        __syncthreads();
        for (int idx = tid; idx < 32 * 256; idx += 256)
            sEmb[idx] = emb[(p * 32 + (idx >> 8)) * EMBED + (idx & 255)];
        __syncthreads();
        for (int v = 0; v < 32; v++) {
            const float* e = &sEmb[v * 256 + lane];
            float s = 0.f;
#pragma unroll
            for (int i = 0; i < 32; i++) s += wreg[i] * e[8 * i];
            s += __shfl_xor_sync(0xffffffffu, s, 1);
            s += __shfl_xor_sync(0xffffffffu, s, 2);
            s += __shfl_xor_sync(0xffffffffu, s, 4);
            if (lane == 0)
                g_tab[(m * VOCAB + p * 32 + v) * HIDDEN + j] = s + bias;
        }
    }
}

// ---------------- kernel 2: transpose hprev [b][k] -> g_h0 [k][b] ----------------
__global__ void k_tr(const float* __restrict__ hprev)
{
    const int o0 = (blockIdx.x * 256 + threadIdx.x) * 4;
#pragma unroll
    for (int i = 0; i < 4; i++) {
        const int o = o0 + i;                    // o < 65536
        const int k = o >> 6, b = o & 63;
        g_h0[k * 64 + b] = hprev[b * HIDDEN + k];
    }
}

// ---------------- kernel 3: one GRU step ----------------
// grid 128 x 256. CTA owns j in [cta*8, cta*8+8), gates r/z/n, all 64 batches.
__global__ void __launch_bounds__(256, 1)
k_step(const int*   __restrict__ x,
       const float* __restrict__ rhw, const float* __restrict__ rhb,
       const float* __restrict__ zhw, const float* __restrict__ zhb,
       const float* __restrict__ nhw, const float* __restrict__ nhb,
       int t)
{
    __shared__ float smem[8192];                 // 2 x (64kk x 64b) h tiles; later aliased by reduction
    const int tid   = threadIdx.x;
    const int cta   = blockIdx.x;
    const int jbase = cta * 8;

    const int kq = tid >> 6;                     // 4-way k split within 64-k tile
    const int s  = tid & 63;
    const int rg = s >> 3;                       // local j (0..7)
    const int bg = s & 7;                        // batch group (8 batches)
    const int j  = jbase + rg;

    const float* prevbase = (t == 0) ? g_h0 : (g_hs + (size_t)(t - 1) * (HIDDEN * BATCH));
    const unsigned smem_u = (unsigned)__cvta_generic_to_shared(smem);

    const float* Wr = rhw + j * HIDDEN;
    const float* Wz = zhw + j * HIDDEN;
    const float* Wn = nhw + j * HIDDEN;

    u64 acc[3][4];
#pragma unroll
    for (int g = 0; g < 3; g++)
#pragma unroll
        for (int p = 0; p < 4; p++) acc[g][p] = 0ull;

    // preload tile 0 (contiguous: [k][b] layout makes tile copy linear)
    {
        const float* src = prevbase;             // k0 = 0
#pragma unroll
        for (int i = 0; i < 4; i++) {
            const int slot = tid + i * 256;      // 1024 float4 slots
            cpasync16(smem_u + slot * 16, src + slot * 4);
        }
        cpcommit();
    }

    for (int kt = 0; kt < 16; ++kt) {
        const int buf = kt & 1;
        if (kt < 15) {
            const float* src = prevbase + (kt + 1) * 64 * 64;
            const unsigned dst = smem_u + (buf ^ 1) * 4096 * 4;
#pragma unroll
            for (int i = 0; i < 4; i++) {
                const int slot = tid + i * 256;
                cpasync16(dst + slot * 16, src + slot * 4);
            }
            cpcommit();
            asm volatile("cp.async.wait_group 1;");
        } else {
            asm volatile("cp.async.wait_group 0;");
        }
        __syncthreads();

        const float* hb = smem + buf * 4096;
        const int kg0 = kt * 64 + kq * 16;
#pragma unroll
        for (int c = 0; c < 4; c++) {
            const int kg = kg0 + c * 4;
            const float4 wr = *(const float4*)(Wr + kg);
            const float4 wz = *(const float4*)(Wz + kg);
            const float4 wn = *(const float4*)(Wn + kg);
#pragma unroll
            for (int i = 0; i < 4; i++) {
                const int kk = kq * 16 + c * 4 + i;
                const u64* hp = (const u64*)(hb + kk * 64 + bg * 8);
                const u64 h0 = hp[0], h1 = hp[1], h2 = hp[2], h3 = hp[3];
                const u64 pr = pack2((&wr.x)[i]);
                const u64 pz = pack2((&wz.x)[i]);
                const u64 pn = pack2((&wn.x)[i]);
                ffma2(acc[0][0], pr, h0); ffma2(acc[0][1], pr, h1);
                ffma2(acc[0][2], pr, h2); ffma2(acc[0][3], pr, h3);
                ffma2(acc[1][0], pz, h0); ffma2(acc[1][1], pz, h1);
                ffma2(acc[1][2], pz, h2); ffma2(acc[1][3], pz, h3);
                ffma2(acc[2][0], pn, h0); ffma2(acc[2][1], pn, h1);
                ffma2(acc[2][2], pn, h2); ffma2(acc[2][3], pn, h3);
            }
        }
        __syncthreads();
    }

    // k-split reduction (alias smem: sRed = smem[0..6144), sPre = smem[6144..7680))
    {
        u64* sRedU = (u64*)smem;
#pragma unroll
        for (int g = 0; g < 3; g++)
#pragma unroll
            for (int p = 0; p < 4; p++)
                sRedU[(kq * 64 + s) * 12 + g * 4 + p] = acc[g][p];
    }
    __syncthreads();
    float* sPre = smem + 6144;
    for (int o = tid; o < 1536; o += 256)
        sPre[o] = smem[o] + smem[1536 + o] + smem[3072 + o] + smem[4608 + o];
    __syncthreads();

    // fused GRU elementwise update: 512 (j,b) outputs
    for (int o = tid; o < 512; o += 256) {
        const int jl = o >> 6, b = o & 63;
        const int jj = jbase + jl;
        const int base = (jl * 8 + (b >> 3)) * 24 + (b & 7);
        const float pr = sPre[base];
        const float pz = sPre[base + 8];
        const float pn = sPre[base + 16];
        const int   v  = x[t * BATCH + b];
        const float ar = g_tab[v * HIDDEN + jj]              + pr + rhb[jj];
        const float az = g_tab[(VOCAB + v) * HIDDEN + jj]    + pz + zhb[jj];
        const float xn = g_tab[(2 * VOCAB + v) * HIDDEN + jj];
        const float r  = fsigmoid(ar);
        const float z  = fsigmoid(az);
        const float n  = tanhf(xn + r * (pn + nhb[jj]));
        const float hp = prevbase[jj * 64 + b];
        g_hs[(size_t)t * (HIDDEN * BATCH) + jj * 64 + b] = (1.f - z) * hp + z * n;
    }
}

// ---------------- kernel 4: logits  out[t*64+b][v] = hs[t][:,b].dw[v] + db[v] ----------------
// grid 256 (one CTA per t) x 256 threads, 2 CTAs/SM.
__global__ void __launch_bounds__(256, 2)
k_logits(const float* __restrict__ dw, const float* __restrict__ db,
         float* __restrict__ out)
{
    __shared__ float smem[8192];                 // double-buffered hs tile
    const int tid = threadIdx.x;
    const int t   = blockIdx.x;
    const int vg  = tid >> 3;                    // 32 groups of 4 v
    const int bg  = tid & 7;                     // 8 batches

    const float* hsrc = g_hs + (size_t)t * (HIDDEN * BATCH);
    const unsigned smem_u = (unsigned)__cvta_generic_to_shared(smem);

    const float* W0 = dw + (vg * 4 + 0) * HIDDEN;
    const float* W1 = dw + (vg * 4 + 1) * HIDDEN;
    const float* W2 = dw + (vg * 4 + 2) * HIDDEN;
    const float* W3 = dw + (vg * 4 + 3) * HIDDEN;

    u64 acc[4][4];
#pragma unroll
    for (int vi = 0; vi < 4; vi++)
#pragma unroll
        for (int p = 0; p < 4; p++) acc[vi][p] = 0ull;

    {
#pragma unroll
        for (int i = 0; i < 4; i++) {
            const int slot = tid + i * 256;
            cpasync16(smem_u + slot * 16, hsrc + slot * 4);
        }
        cpcommit();
    }

    for (int kt = 0; kt < 16; ++kt) {
        const int buf = kt & 1;
        if (kt < 15) {
            const float* src = hsrc + (kt + 1) * 64 * 64;
            const unsigned dst = smem_u + (buf ^ 1) * 4096 * 4;
#pragma unroll
            for (int i = 0; i < 4; i++) {
                const int slot = tid + i * 256;
                cpasync16(dst + slot * 16, src + slot * 4);
            }
            cpcommit();
            asm volatile("cp.async.wait_group 1;");
        } else {
            asm volatile("cp.async.wait_group 0;");
        }
        __syncthreads();

        const float* hb = smem + buf * 4096;
        const int kg0 = kt * 64;
#pragma unroll 4
        for (int c = 0; c < 16; c++) {
            const int kg = kg0 + c * 4;
            const float4 w0 = *(const float4*)(W0 + kg);
            const float4 w1 = *(const float4*)(W1 + kg);
            const float4 w2 = *(const float4*)(W2 + kg);
            const float4 w3 = *(const float4*)(W3 + kg);
#pragma unroll
            for (int i = 0; i < 4; i++) {
                const int kk = c * 4 + i;
                const u64* hp = (const u64*)(hb + kk * 64 + bg * 8);
                const u64 h0 = hp[0], h1 = hp[1], h2 = hp[2], h3 = hp[3];
                const u64 p0 = pack2((&w0.x)[i]);
                const u64 p1 = pack2((&w1.x)[i]);
                const u64 p2 = pack2((&w2.x)[i]);
                const u64 p3 = pack2((&w3.x)[i]);
                ffma2(acc[0][0], p0, h0); ffma2(acc[0][1], p0, h1);
                ffma2(acc[0][2], p0, h2); ffma2(acc[0][3], p0, h3);
                ffma2(acc[1][0], p1, h0); ffma2(acc[1][1], p1, h1);
                ffma2(acc[1][2], p1, h2); ffma2(acc[1][3], p1, h3);
                ffma2(acc[2][0], p2, h0); ffma2(acc[2][1], p2, h1);
                ffma2(acc[2][2], p2, h2); ffma2(acc[2][3], p2, h3);
                ffma2(acc[3][0], p3, h0); ffma2(acc[3][1], p3, h1);
                ffma2(acc[3][2], p3, h2); ffma2(acc[3][3], p3, h3);
            }
        }
        __syncthreads();
    }

    const float4 dbv = *(const float4*)(db + vg * 4);
#pragma unroll
    for (int p = 0; p < 4; p++) {
        float l0, h0, l1, h1, l2, h2, l3, h3;
        unpack2(acc[0][p], l0, h0); unpack2(acc[1][p], l1, h1);
        unpack2(acc[2][p], l2, h2); unpack2(acc[3][p], l3, h3);
        const int b0 = bg * 8 + 2 * p;
        float4 r0 = make_float4(l0 + dbv.x, l1 + dbv.y, l2 + dbv.z, l3 + dbv.w);
        float4 r1 = make_float4(h0 + dbv.x, h1 + dbv.y, h2 + dbv.z, h3 + dbv.w);
        *(float4*)(out + (size_t)(t * 64 + b0    ) * VOCAB + vg * 4) = r0;
        *(float4*)(out + (size_t)(t * 64 + b0 + 1) * VOCAB + vg * 4) = r1;
    }
}

// ---------------- kernel 5: h_final  out2[b][k] = hs[255][k][b] ----------------
__global__ void k_final(float* __restrict__ out2)
{
    const int o0 = (blockIdx.x * 256 + threadIdx.x) * 4;
    const float* src = g_hs + (size_t)(SEQ - 1) * (HIDDEN * BATCH);
#pragma unroll
    for (int i = 0; i < 4; i++) {
        const int o = o0 + i;                    // o < 65536
        const int b = o >> 10, k = o & 1023;
        out2[b * HIDDEN + k] = src[k * 64 + b];
    }
}

// ---------------- launcher ----------------
extern "C" void kernel_launch(void* const* d_in, const int* in_sizes, int n_in,
                              void* d_out, int out_size)
{
    const int*   x    = (const int*)  d_in[0];
    const float* hprev= (const float*)d_in[1];
    const float* emb  = (const float*)d_in[2];
    const float* rxw  = (const float*)d_in[3];
    const float* rxb  = (const float*)d_in[4];
    const float* rhw  = (const float*)d_in[5];
    const float* rhb  = (const float*)d_in[6];
    const float* zxw  = (const float*)d_in[7];
    const float* zxb  = (const float*)d_in[8];
    const float* zhw  = (const float*)d_in[9];
    const float* zhb  = (const float*)d_in[10];
    const float* nxw  = (const float*)d_in[11];
    const float* nxb  = (const float*)d_in[12];
    const float* nhw  = (const float*)d_in[13];
    const float* nhb  = (const float*)d_in[14];
    const float* dw   = (const float*)d_in[15];
    const float* db   = (const float*)d_in[16];
    float* out = (float*)d_out;

    k_tables<<<dim3(32, 3), 256>>>(emb, rxw, zxw, nxw, rxb, zxb, nxb);
    k_tr<<<64, 256>>>(hprev);
    for (int t = 0; t < SEQ; ++t)
        k_step<<<128, 256>>>(x, rhw, rhb, zhw, zhb, nhw, nhb, t);
    k_logits<<<256, 256>>>(dw, db, out);
    k_final<<<64, 256>>>(out + (size_t)SEQ * BATCH * VOCAB);
}

// round 3
// speedup vs baseline: 1.1270x; 1.1270x over previous
#include <cuda_runtime.h>
#include <cuda_bf16.h>
#include <cstdint>

#define SEQ    256
#define BATCH  64
#define VOCAB  128
#define EMBED  256
#define HIDDEN 1024
#define NCTA   128
#define SWP    1028   // padded weight row stride (floats): rg rows land in disjoint banks

typedef unsigned long long u64;

// ---------------- device scratch (allocations forbidden) ----------------
__device__ float g_tab[3 * VOCAB * HIDDEN];            // input projections per vocab id (incl. x-bias)
__device__ float g_h0 [HIDDEN * BATCH];                // hprev transposed to [k][b]
__device__ float g_hs [(size_t)SEQ * HIDDEN * BATCH];  // hidden states, [t][k][b]
__device__ volatile unsigned g_flag[NCTA];             // global barrier flags (reset at kernel end)
__device__ volatile unsigned g_release;                // global barrier release word

// ---------------- helpers ----------------
__device__ __forceinline__ u64 pack2(float x) {
    u64 r; asm("mov.b64 %0, {%1, %1};" : "=l"(r) : "f"(x)); return r;
}
__device__ __forceinline__ void ffma2(u64& d, u64 a, u64 b) {
    asm volatile("fma.rn.f32x2 %0, %1, %2, %0;" : "+l"(d) : "l"(a), "l"(b));
}
__device__ __forceinline__ void unpack2(u64 v, float& lo, float& hi) {
    asm("mov.b64 {%0, %1}, %2;" : "=f"(lo), "=f"(hi) : "l"(v));
}
__device__ __forceinline__ void cpasync16(unsigned saddr, const void* gaddr) {
    asm volatile("cp.async.cg.shared.global [%0], [%1], 16;" :: "r"(saddr), "l"(gaddr));
}
__device__ __forceinline__ void cpcommit() { asm volatile("cp.async.commit_group;"); }

__device__ __forceinline__ float fsigmoid(float a) {
    return __fdividef(1.f, 1.f + __expf(-a));
}

// ---------------- kernel 1: vocab tables  tab[m][v][j] = emb[v].W_mx[j] + b_mx[j] ----------------
__global__ void k_tables(const float* __restrict__ emb,
                         const float* __restrict__ rxw, const float* __restrict__ zxw,
                         const float* __restrict__ nxw,
                         const float* __restrict__ rxb, const float* __restrict__ zxb,
                         const float* __restrict__ nxb)
{
    __shared__ float sEmb[32 * 256];
    const int tid  = threadIdx.x;
    const int m    = blockIdx.y;
    const int j    = blockIdx.x * 32 + (tid >> 3);
    const int lane = tid & 7;

    const float* W = (m == 0) ? rxw : (m == 1) ? zxw : nxw;
    const float* B = (m == 0) ? rxb : (m == 1) ? zxb : nxb;

    float wreg[32];
#pragma unroll
    for (int i = 0; i < 32; i++) wreg[i] = W[j * EMBED + lane + 8 * i];
    const float bias = B[j];

    for (int p = 0; p < 4; p++) {
        __syncthreads();
        for (int idx = tid; idx < 32 * 256; idx += 256)
            sEmb[idx] = emb[(p * 32 + (idx >> 8)) * EMBED + (idx & 255)];
        __syncthreads();
        for (int v = 0; v < 32; v++) {
            const float* e = &sEmb[v * 256 + lane];
            float s = 0.f;
#pragma unroll
            for (int i = 0; i < 32; i++) s += wreg[i] * e[8 * i];
            s += __shfl_xor_sync(0xffffffffu, s, 1);
            s += __shfl_xor_sync(0xffffffffu, s, 2);
            s += __shfl_xor_sync(0xffffffffu, s, 4);
            if (lane == 0)
                g_tab[(m * VOCAB + p * 32 + v) * HIDDEN + j] = s + bias;
        }
    }
}

// ---------------- kernel 2: transpose hprev [b][k] -> g_h0 [k][b] ----------------
__global__ void k_tr(const float* __restrict__ hprev)
{
    const int o0 = (blockIdx.x * 256 + threadIdx.x) * 4;
#pragma unroll
    for (int i = 0; i < 4; i++) {
        const int o = o0 + i;
        const int k = o >> 6, b = o & 63;
        g_h0[k * 64 + b] = hprev[b * HIDDEN + k];
    }
}

// ---------------- global barrier (inside persistent kernel) ----------------
__device__ __forceinline__ void gbar(unsigned t)
{
    __syncthreads();
    if (threadIdx.x == 0) { __threadfence(); g_flag[blockIdx.x] = t; }
    if (blockIdx.x == 0) {
        if (threadIdx.x < NCTA)
            while (g_flag[threadIdx.x] < t) __nanosleep(32);
        __syncthreads();
        if (threadIdx.x == 0) g_release = t;
    } else {
        if (threadIdx.x == 0)
            while (g_release < t) __nanosleep(32);
    }
    __syncthreads();
    __threadfence();
}

// ---------------- kernel 3: persistent GRU recurrence ----------------
// 128 CTAs x 256 threads, 1/SM. CTA owns hidden units [cta*8, cta*8+8).
// smem: weights 24x1028 | h tiles 2x4096 (aliased by sRed/sPre) | tab 3072 | bias 32 | tok 64
__global__ void __launch_bounds__(256, 1)
k_recur(const int*   __restrict__ x,
        const float* __restrict__ rhw, const float* __restrict__ rhb,
        const float* __restrict__ zhw, const float* __restrict__ zhb,
        const float* __restrict__ nhw, const float* __restrict__ nhb)
{
    extern __shared__ float sm[];
    float* sW    = sm;                         // 24 * SWP = 24672 floats
    float* sTile = sW + 24 * SWP;              // 8192 floats (double-buffered h tile)
    float* sTab  = sTile + 8192;               // 3072 floats
    float* sBias = sTab + 3072;                // 32 floats
    int*   sTok  = (int*)(sBias + 32);         // 64 ints

    const int tid   = threadIdx.x;
    const int cta   = blockIdx.x;
    const int jbase = cta * 8;

    // ---- one-time loads ----
    for (int idx = tid; idx < 24 * HIDDEN; idx += 256) {
        const int r = idx >> 10, k = idx & 1023;
        const int jl = r / 3, g = r % 3;       // row layout: (jl*3 + g)
        const float* W = (g == 0) ? rhw : (g == 1) ? zhw : nhw;
        sW[r * SWP + k] = W[(jbase + jl) * HIDDEN + k];
    }
    if (tid < 24) {
        const int g = tid >> 3, jl = tid & 7;  // sBias: [0..7]=r, [8..15]=z, [16..23]=n
        const float* B = (g == 0) ? rhb : (g == 1) ? zhb : nhb;
        sBias[tid] = B[jbase + jl];
    }
    for (int idx = tid; idx < 3072; idx += 256) {
        const int jl = idx & 7, mv = idx >> 3;
        sTab[idx] = g_tab[mv * HIDDEN + jbase + jl];
    }
    __syncthreads();

    const int kq = tid >> 6;                   // 4-way k split
    const int s  = tid & 63;
    const int rg = s >> 3;                     // local j row 0..7
    const int bg = s & 7;                      // batch group of 8
    const unsigned tile_u = (unsigned)__cvta_generic_to_shared(sTile);

    const float* sWr = sW + (rg * 3 + 0) * SWP;
    const float* sWz = sW + (rg * 3 + 1) * SWP;
    const float* sWn = sW + (rg * 3 + 2) * SWP;

    for (int t = 0; t < SEQ; ++t) {
        if (tid < 64) sTok[tid] = x[t * BATCH + tid];

        const float* prevbase = (t == 0) ? g_h0
                              : (g_hs + (size_t)(t - 1) * (HIDDEN * BATCH));

        u64 acc[3][4];
#pragma unroll
        for (int g = 0; g < 3; g++)
#pragma unroll
            for (int p = 0; p < 4; p++) acc[g][p] = 0ull;

        // prefetch tile 0
#pragma unroll
        for (int i = 0; i < 4; i++) {
            const int slot = tid + i * 256;
            cpasync16(tile_u + slot * 16, prevbase + slot * 4);
        }
        cpcommit();

        for (int kt = 0; kt < 16; ++kt) {
            const int buf = kt & 1;
            if (kt < 15) {
                const float* src = prevbase + (kt + 1) * 64 * 64;
                const unsigned dst = tile_u + (buf ^ 1) * 4096 * 4;
#pragma unroll
                for (int i = 0; i < 4; i++) {
                    const int slot = tid + i * 256;
                    cpasync16(dst + slot * 16, src + slot * 4);
                }
                cpcommit();
                asm volatile("cp.async.wait_group 1;");
            } else {
                asm volatile("cp.async.wait_group 0;");
            }
            __syncthreads();

            const float* hb  = sTile + buf * 4096;
            const int    kg0 = kt * 64 + kq * 16;
#pragma unroll
            for (int c = 0; c < 4; c++) {
                const int kg = kg0 + c * 4;
                const float4 wr = *(const float4*)(sWr + kg);
                const float4 wz = *(const float4*)(sWz + kg);
                const float4 wn = *(const float4*)(sWn + kg);
#pragma unroll
                for (int i = 0; i < 4; i++) {
                    const int kk = kq * 16 + c * 4 + i;
                    const u64* hp = (const u64*)(hb + kk * 64 + bg * 8);
                    const u64 h0 = hp[0], h1 = hp[1], h2 = hp[2], h3 = hp[3];
                    const u64 pr = pack2((&wr.x)[i]);
                    const u64 pz = pack2((&wz.x)[i]);
                    const u64 pn = pack2((&wn.x)[i]);
                    ffma2(acc[0][0], pr, h0); ffma2(acc[0][1], pr, h1);
                    ffma2(acc[0][2], pr, h2); ffma2(acc[0][3], pr, h3);
                    ffma2(acc[1][0], pz, h0); ffma2(acc[1][1], pz, h1);
                    ffma2(acc[1][2], pz, h2); ffma2(acc[1][3], pz, h3);
                    ffma2(acc[2][0], pn, h0); ffma2(acc[2][1], pn, h1);
                    ffma2(acc[2][2], pn, h2); ffma2(acc[2][3], pn, h3);
                }
            }
            __syncthreads();
        }

        // k-split reduction: alias sTile as sRed[6144] + sPre[1536]
        {
            u64* sRedU = (u64*)sTile;
#pragma unroll
            for (int g = 0; g < 3; g++)
#pragma unroll
                for (int p = 0; p < 4; p++)
                    sRedU[(kq * 64 + s) * 12 + g * 4 + p] = acc[g][p];
        }
        __syncthreads();
        float* sPre = sTile + 6144;
        for (int o = tid; o < 1536; o += 256)
            sPre[o] = sTile[o] + sTile[1536 + o] + sTile[3072 + o] + sTile[4608 + o];
        __syncthreads();

        // fused GRU elementwise update
        float* hout = g_hs + (size_t)t * (HIDDEN * BATCH);
        for (int o = tid; o < 512; o += 256) {
            const int jl = o >> 6, b = o & 63;
            const int jj = jbase + jl;
            const int base = (jl * 8 + (b >> 3)) * 24 + (b & 7);
            const float pr = sPre[base];
            const float pz = sPre[base + 8];
            const float pn = sPre[base + 16];
            const int   v  = sTok[b];
            const float ar = sTab[v * 8 + jl]          + pr + sBias[jl];
            const float az = sTab[(128 + v) * 8 + jl]  + pz + sBias[8 + jl];
            const float xn = sTab[(256 + v) * 8 + jl];
            const float r  = fsigmoid(ar);
            const float z  = fsigmoid(az);
            const float n  = tanhf(xn + r * (pn + sBias[16 + jl]));
            const float hp = prevbase[jj * 64 + b];
            hout[jj * 64 + b] = (1.f - z) * hp + z * n;
        }

        if (t < SEQ - 1) gbar((unsigned)(t + 1));
    }

    // ---- reset barrier state for graph replays ----
    __syncthreads();
    if (threadIdx.x == 0) g_flag[cta] = 0;       // signals: this CTA fully done with barriers
    if (cta == 0) {
        if (threadIdx.x < NCTA)
            while (g_flag[threadIdx.x] != 0) __nanosleep(64);
        __syncthreads();
        if (threadIdx.x == 0) g_release = 0;
    }
}

// ---------------- kernel 4: logits ----------------
__global__ void __launch_bounds__(256, 2)
k_logits(const float* __restrict__ dw, const float* __restrict__ db,
         float* __restrict__ out)
{
    __shared__ float smem[8192];
    const int tid = threadIdx.x;
    const int t   = blockIdx.x;
    const int vg  = tid >> 3;
    const int bg  = tid & 7;

    const float* hsrc = g_hs + (size_t)t * (HIDDEN * BATCH);
    const unsigned smem_u = (unsigned)__cvta_generic_to_shared(smem);

    const float* W0 = dw + (vg * 4 + 0) * HIDDEN;
    const float* W1 = dw + (vg * 4 + 1) * HIDDEN;
    const float* W2 = dw + (vg * 4 + 2) * HIDDEN;
    const float* W3 = dw + (vg * 4 + 3) * HIDDEN;

    u64 acc[4][4];
#pragma unroll
    for (int vi = 0; vi < 4; vi++)
#pragma unroll
        for (int p = 0; p < 4; p++) acc[vi][p] = 0ull;

    {
#pragma unroll
        for (int i = 0; i < 4; i++) {
            const int slot = tid + i * 256;
            cpasync16(smem_u + slot * 16, hsrc + slot * 4);
        }
        cpcommit();
    }

    for (int kt = 0; kt < 16; ++kt) {
        const int buf = kt & 1;
        if (kt < 15) {
            const float* src = hsrc + (kt + 1) * 64 * 64;
            const unsigned dst = smem_u + (buf ^ 1) * 4096 * 4;
#pragma unroll
            for (int i = 0; i < 4; i++) {
                const int slot = tid + i * 256;
                cpasync16(dst + slot * 16, src + slot * 4);
            }
            cpcommit();
            asm volatile("cp.async.wait_group 1;");
        } else {
            asm volatile("cp.async.wait_group 0;");
        }
        __syncthreads();

        const float* hb = smem + buf * 4096;
        const int kg0 = kt * 64;
#pragma unroll 4
        for (int c = 0; c < 16; c++) {
            const int kg = kg0 + c * 4;
            const float4 w0 = *(const float4*)(W0 + kg);
            const float4 w1 = *(const float4*)(W1 + kg);
            const float4 w2 = *(const float4*)(W2 + kg);
            const float4 w3 = *(const float4*)(W3 + kg);
#pragma unroll
            for (int i = 0; i < 4; i++) {
                const int kk = c * 4 + i;
                const u64* hp = (const u64*)(hb + kk * 64 + bg * 8);
                const u64 h0 = hp[0], h1 = hp[1], h2 = hp[2], h3 = hp[3];
                const u64 p0 = pack2((&w0.x)[i]);
                const u64 p1 = pack2((&w1.x)[i]);
                const u64 p2 = pack2((&w2.x)[i]);
                const u64 p3 = pack2((&w3.x)[i]);
                ffma2(acc[0][0], p0, h0); ffma2(acc[0][1], p0, h1);
                ffma2(acc[0][2], p0, h2); ffma2(acc[0][3], p0, h3);
                ffma2(acc[1][0], p1, h0); ffma2(acc[1][1], p1, h1);
                ffma2(acc[1][2], p1, h2); ffma2(acc[1][3], p1, h3);
                ffma2(acc[2][0], p2, h0); ffma2(acc[2][1], p2, h1);
                ffma2(acc[2][2], p2, h2); ffma2(acc[2][3], p2, h3);
                ffma2(acc[3][0], p3, h0); ffma2(acc[3][1], p3, h1);
                ffma2(acc[3][2], p3, h2); ffma2(acc[3][3], p3, h3);
            }
        }
        __syncthreads();
    }

    const float4 dbv = *(const float4*)(db + vg * 4);
#pragma unroll
    for (int p = 0; p < 4; p++) {
        float l0, h0, l1, h1, l2, h2, l3, h3;
        unpack2(acc[0][p], l0, h0); unpack2(acc[1][p], l1, h1);
        unpack2(acc[2][p], l2, h2); unpack2(acc[3][p], l3, h3);
        const int b0 = bg * 8 + 2 * p;
        float4 r0 = make_float4(l0 + dbv.x, l1 + dbv.y, l2 + dbv.z, l3 + dbv.w);
        float4 r1 = make_float4(h0 + dbv.x, h1 + dbv.y, h2 + dbv.z, h3 + dbv.w);
        *(float4*)(out + (size_t)(t * 64 + b0    ) * VOCAB + vg * 4) = r0;
        *(float4*)(out + (size_t)(t * 64 + b0 + 1) * VOCAB + vg * 4) = r1;
    }
}

// ---------------- kernel 5: h_final ----------------
__global__ void k_final(float* __restrict__ out2)
{
    const int o0 = (blockIdx.x * 256 + threadIdx.x) * 4;
    const float* src = g_hs + (size_t)(SEQ - 1) * (HIDDEN * BATCH);
#pragma unroll
    for (int i = 0; i < 4; i++) {
        const int o = o0 + i;
        const int b = o >> 10, k = o & 1023;
        out2[b * HIDDEN + k] = src[k * 64 + b];
    }
}

// ---------------- launcher ----------------
extern "C" void kernel_launch(void* const* d_in, const int* in_sizes, int n_in,
                              void* d_out, int out_size)
{
    const int*   x    = (const int*)  d_in[0];
    const float* hprev= (const float*)d_in[1];
    const float* emb  = (const float*)d_in[2];
    const float* rxw  = (const float*)d_in[3];
    const float* rxb  = (const float*)d_in[4];
    const float* rhw  = (const float*)d_in[5];
    const float* rhb  = (const float*)d_in[6];
    const float* zxw  = (const float*)d_in[7];
    const float* zxb  = (const float*)d_in[8];
    const float* zhw  = (const float*)d_in[9];
    const float* zhb  = (const float*)d_in[10];
    const float* nxw  = (const float*)d_in[11];
    const float* nxb  = (const float*)d_in[12];
    const float* nhw  = (const float*)d_in[13];
    const float* nhb  = (const float*)d_in[14];
    const float* dw   = (const float*)d_in[15];
    const float* db   = (const float*)d_in[16];
    float* out = (float*)d_out;

    const int smem_bytes = (24 * SWP + 8192 + 3072 + 32) * 4 + 64 * 4;
    static bool attr_set = false;
    if (!attr_set) {
        cudaFuncSetAttribute(k_recur, cudaFuncAttributeMaxDynamicSharedMemorySize, smem_bytes);
        attr_set = true;
    }

    k_tables<<<dim3(32, 3), 256>>>(emb, rxw, zxw, nxw, rxb, zxb, nxb);
    k_tr<<<64, 256>>>(hprev);
    k_recur<<<NCTA, 256, smem_bytes>>>(x, rhw, rhb, zhw, zhb, nhw, nhb);
    k_logits<<<256, 256>>>(dw, db, out);
    k_final<<<64, 256>>>(out + (size_t)SEQ * BATCH * VOCAB);
}